// round 15
// baseline (speedup 1.0000x reference)
#include <cuda_runtime.h>
#include <cuda_bf16.h>
#include <math.h>
#include <stdint.h>

#define NROWS 8192
#define DIMK  512
#define KTOP  10
#define CAND  16
#define SCALE 0.04419417382415922f   // 512^-0.5

// Scratch (bss): fp32 embeddings (unscaled) + bf16 copies + candidate lists
__device__ float          g_eh[NROWS * DIMK];
__device__ float          g_et[NROWS * DIMK];
__device__ __nv_bfloat16  g_bh[NROWS * DIMK];
__device__ __nv_bfloat16  g_bt[NROWS * DIMK];
__device__ int            g_cand[NROWS * CAND];

// ---------------------------------------------------------------------------
// sm_80-era primitives (base compute_103 target — no tcgen05)
// ---------------------------------------------------------------------------
__device__ __forceinline__ uint32_t smem_to_u32(const void* p) {
    uint32_t a;
    asm("{ .reg .u64 t; cvta.to.shared.u64 t, %1; cvt.u32.u64 %0, t; }" : "=r"(a) : "l"(p));
    return a;
}
__device__ __forceinline__ void ldsm4(uint32_t& r0, uint32_t& r1, uint32_t& r2, uint32_t& r3,
                                      uint32_t addr) {
    asm volatile("ldmatrix.sync.aligned.m8n8.x4.shared.b16 {%0,%1,%2,%3}, [%4];"
                 : "=r"(r0), "=r"(r1), "=r"(r2), "=r"(r3) : "r"(addr));
}
__device__ __forceinline__ void mma16816(float* c, const uint32_t* a, uint32_t b0, uint32_t b1) {
    asm volatile(
        "mma.sync.aligned.m16n8k16.row.col.f32.bf16.bf16.f32 "
        "{%0,%1,%2,%3}, {%4,%5,%6,%7}, {%8,%9}, {%0,%1,%2,%3};"
        : "+f"(c[0]), "+f"(c[1]), "+f"(c[2]), "+f"(c[3])
        : "r"(a[0]), "r"(a[1]), "r"(a[2]), "r"(a[3]), "r"(b0), "r"(b1));
}
#define CP_ASYNC16(dst, src) \
    asm volatile("cp.async.ca.shared.global [%0], [%1], 16;" :: "r"(dst), "l"(src))
#define CP_COMMIT() asm volatile("cp.async.commit_group;" ::: "memory")
#define CP_WAIT(n)  asm volatile("cp.async.wait_group %0;" :: "n"(n) : "memory")
#define SW128(b) ((b) ^ (((b) >> 3) & 0x70))

// ---------------------------------------------------------------------------
// Kernel A: E = X @ W^T + b (UNSCALED), fp32 + bf16 out. (~90% of fp32 peak)
// ---------------------------------------------------------------------------
__global__ void embed_kernel(const float* __restrict__ X,
                             const float* __restrict__ W0, const float* __restrict__ b0,
                             const float* __restrict__ W1, const float* __restrict__ b1)
{
    const int z = blockIdx.z;
    const float* W    = z ? W1 : W0;
    const float* bias = z ? b1 : b0;
    float* of         = z ? g_et : g_eh;
    __nv_bfloat16* ob = z ? g_bt : g_bh;

    __shared__ float Xs[32][64];
    __shared__ float Ws[32][128];

    const int tid = threadIdx.x;
    const int rb = blockIdx.y * 64;
    const int cb = blockIdx.x * 128;
    const int ty = tid >> 5;
    const int tx = tid & 31;

    float acc[8][4];
    #pragma unroll
    for (int i = 0; i < 8; i++)
        #pragma unroll
        for (int j = 0; j < 4; j++) acc[i][j] = 0.f;

    const int lr  = tid & 63;
    const int lk  = (tid >> 6) * 8;
    const int lrw = tid & 127;
    const int lkw = (tid >> 7) * 16;

    for (int kc = 0; kc < DIMK; kc += 32) {
        __syncthreads();
        #pragma unroll
        for (int j = 0; j < 8; j += 4) {
            float4 xv = *(const float4*)(X + (size_t)(rb + lr) * DIMK + kc + lk + j);
            Xs[lk + j + 0][lr] = xv.x; Xs[lk + j + 1][lr] = xv.y;
            Xs[lk + j + 2][lr] = xv.z; Xs[lk + j + 3][lr] = xv.w;
        }
        #pragma unroll
        for (int j = 0; j < 16; j += 4) {
            float4 wv = *(const float4*)(W + (size_t)(cb + lrw) * DIMK + kc + lkw + j);
            Ws[lkw + j + 0][lrw] = wv.x; Ws[lkw + j + 1][lrw] = wv.y;
            Ws[lkw + j + 2][lrw] = wv.z; Ws[lkw + j + 3][lrw] = wv.w;
        }
        __syncthreads();
        #pragma unroll
        for (int k = 0; k < 32; k++) {
            float4 a0 = *(const float4*)&Xs[k][ty * 8];
            float4 a1 = *(const float4*)&Xs[k][ty * 8 + 4];
            float4 b  = *(const float4*)&Ws[k][tx * 4];
            float av[8] = {a0.x, a0.y, a0.z, a0.w, a1.x, a1.y, a1.z, a1.w};
            float bv[4] = {b.x, b.y, b.z, b.w};
            #pragma unroll
            for (int i = 0; i < 8; i++)
                #pragma unroll
                for (int j = 0; j < 4; j++)
                    acc[i][j] = fmaf(av[i], bv[j], acc[i][j]);
        }
    }

    float bv[4];
    #pragma unroll
    for (int j = 0; j < 4; j++) bv[j] = bias[cb + tx * 4 + j];
    #pragma unroll
    for (int i = 0; i < 8; i++) {
        int row = rb + ty * 8 + i;
        size_t base = (size_t)row * DIMK + cb + tx * 4;
        float e[4];
        #pragma unroll
        for (int j = 0; j < 4; j++) e[j] = acc[i][j] + bv[j];
        *(float4*)(of + base) = make_float4(e[0], e[1], e[2], e[3]);
        __nv_bfloat162 p0, p1;
        p0.x = __float2bfloat16_rn(e[0]); p0.y = __float2bfloat16_rn(e[1]);
        p1.x = __float2bfloat16_rn(e[2]); p1.y = __float2bfloat16_rn(e[3]);
        *(__nv_bfloat162*)(ob + base)     = p0;
        *(__nv_bfloat162*)(ob + base + 2) = p1;
    }
}

// ---------------------------------------------------------------------------
// Kernel B: bf16 HMMA approx logits + warp-parallel register top-16 select.
// 512 thr (16 warps, 2x8 grid of 32x32 warp tiles), 64-row stripe/block,
// N-tiles of 256, 64-k chunks, 2x32KB B double buffer.
// ---------------------------------------------------------------------------
#define MBLK   64
#define NTILE  256
#define KC     64
#define NCHUNK (DIMK / KC)                  // 8
#define GTOT   ((NROWS / NTILE) * NCHUNK)   // 256 global chunks

#define OFF_A      0                        // 8 sub-tiles x 8192 B = 65536
#define OFF_B      65536                    // 2 x 32768 = 65536
#define OFF_STAGE  131072                   // 64 x 260 x 4 = 66560
#define STAGE_STRIDE 260
#define SMEM_LG    197632

__global__ void __launch_bounds__(512, 1)
logits_cand_kernel()
{
    extern __shared__ char smem[];
    const uint32_t smem_base = smem_to_u32(smem);
    const int tid  = threadIdx.x;
    const int wid  = tid >> 5;
    const int lane = tid & 31;
    const int rb   = blockIdx.x * MBLK;

    const int m_base = (wid >> 3) * 32;
    const int n_base = (wid & 7) * 32;

    float* stage = (float*)(smem + OFF_STAGE);

    // register-resident sorted top-16: warp owns rows 4*wid..4*wid+3,
    // lanes 0..15 hold slots (sorted desc, ties idx asc). Lanes 16-31 hold
    // evicted history; any evicted value < current threshold, so those lanes
    // can never pass the insertion ballot — p stays correct.
    float lv[4]; int li[4];
    #pragma unroll
    for (int q = 0; q < 4; q++) { lv[q] = -INFINITY; li[q] = 0; }

    const int mat = lane >> 3, r8 = lane & 7;
    const int aoff_m = ((mat & 1) << 3) + r8;
    const int aoff_k = (mat >> 1) << 4;
    const int boff_n = ((mat >> 1) << 3) + r8;
    const int boff_k = (mat & 1) << 4;

    // A stripe: 64 rows x 512 k bf16 -> 8 sub-tiles
    #pragma unroll
    for (int t = 0; t < 8; t++) {
        int idx = tid + t * 512;
        int c = idx >> 9, rem = idx & 511, r = rem >> 3, g = rem & 7;
        const __nv_bfloat16* src = g_bh + (size_t)(rb + r) * DIMK + c * KC + g * 8;
        uint32_t dst = smem_base + OFF_A + c * 8192 + SW128(r * 128 + g * 16);
        CP_ASYNC16(dst, src);
    }

    auto issue_B = [&](int g) {
        const int cbase = (g >> 3) * NTILE;
        const int koff  = (g & 7) * KC;
        const int buf   = g & 1;
        #pragma unroll
        for (int t = 0; t < 4; t++) {
            int rem = tid + t * 512;
            int r = rem >> 3, gg = rem & 7;
            const __nv_bfloat16* src = g_bt + (size_t)(cbase + r) * DIMK + koff + gg * 8;
            uint32_t dst = smem_base + OFF_B + buf * 32768 + SW128(r * 128 + gg * 16);
            CP_ASYNC16(dst, src);
        }
    };

    issue_B(0); CP_COMMIT();

    float acc[2][4][4];

    for (int ct = 0; ct < NROWS / NTILE; ct++) {
        const int cbase = ct * NTILE;

        #pragma unroll
        for (int fm = 0; fm < 2; fm++)
            #pragma unroll
            for (int fn = 0; fn < 4; fn++)
                #pragma unroll
                for (int q = 0; q < 4; q++) acc[fm][fn][q] = 0.f;

        for (int kc = 0; kc < NCHUNK; kc++) {
            const int g = ct * NCHUNK + kc;
            if (g + 1 < GTOT) { issue_B(g + 1); CP_COMMIT(); CP_WAIT(1); }
            else              { CP_WAIT(0); }
            __syncthreads();

            const uint32_t Ab = smem_base + OFF_A + kc * 8192;
            const uint32_t Bb = smem_base + OFF_B + (g & 1) * 32768;

            #pragma unroll
            for (int k16 = 0; k16 < KC / 16; k16++) {
                const int kbyte = k16 * 32;
                uint32_t Af[2][4];
                #pragma unroll
                for (int fm = 0; fm < 2; fm++)
                    ldsm4(Af[fm][0], Af[fm][1], Af[fm][2], Af[fm][3],
                          Ab + SW128((m_base + fm * 16 + aoff_m) * 128 + kbyte + aoff_k));
                uint32_t Bf[2][4];
                #pragma unroll
                for (int fp = 0; fp < 2; fp++)
                    ldsm4(Bf[fp][0], Bf[fp][1], Bf[fp][2], Bf[fp][3],
                          Bb + SW128((n_base + fp * 16 + boff_n) * 128 + kbyte + boff_k));
                #pragma unroll
                for (int fm = 0; fm < 2; fm++) {
                    mma16816(acc[fm][0], Af[fm], Bf[0][0], Bf[0][1]);
                    mma16816(acc[fm][1], Af[fm], Bf[0][2], Bf[0][3]);
                    mma16816(acc[fm][2], Af[fm], Bf[1][0], Bf[1][1]);
                    mma16816(acc[fm][3], Af[fm], Bf[1][2], Bf[1][3]);
                }
            }
            __syncthreads();
        }

        // stage 64x256 approx logits (stride 260)
        #pragma unroll
        for (int fm = 0; fm < 2; fm++)
            #pragma unroll
            for (int fn = 0; fn < 4; fn++) {
                int row = m_base + fm * 16 + (lane >> 2);
                int col = n_base + fn * 8 + (lane & 3) * 2;
                *(float2*)(stage + row * STAGE_STRIDE + col) =
                    make_float2(acc[fm][fn][0], acc[fm][fn][1]);
                *(float2*)(stage + (row + 8) * STAGE_STRIDE + col) =
                    make_float2(acc[fm][fn][2], acc[fm][fn][3]);
            }
        __syncthreads();

        // warp-parallel select: warp handles rows 4*wid..4*wid+3
        #pragma unroll
        for (int q = 0; q < 4; q++) {
            const int row = wid * 4 + q;
            const float* crow = stage + row * STAGE_STRIDE;
            float kv = __shfl_sync(0xffffffffu, lv[q], CAND - 1);
            #pragma unroll
            for (int j = 0; j < 8; j++) {
                float v = crow[32 * j + lane];
                unsigned m = __ballot_sync(0xffffffffu, v > kv);
                while (m) {
                    int b = __ffs(m) - 1; m &= m - 1;
                    float vb = __shfl_sync(0xffffffffu, v, b);
                    int   cb = cbase + 32 * j + b;
                    unsigned gt = __ballot_sync(0xffffffffu,
                        (lv[q] > vb) || (lv[q] == vb && li[q] < cb));
                    int p = __popc(gt);
                    if (p < CAND) {
                        float pv = __shfl_up_sync(0xffffffffu, lv[q], 1);
                        int   pi = __shfl_up_sync(0xffffffffu, li[q], 1);
                        if (lane > p)  { lv[q] = pv; li[q] = pi; }
                        if (lane == p) { lv[q] = vb; li[q] = cb; }
                        kv = __shfl_sync(0xffffffffu, lv[q], CAND - 1);
                    }
                }
            }
        }
    }

    #pragma unroll
    for (int q = 0; q < 4; q++)
        if (lane < CAND)
            g_cand[(size_t)(rb + wid * 4 + q) * CAND + lane] = li[q];
}

// ---------------------------------------------------------------------------
// Kernel C: EXACT fp32 rerank (k-sequential per-lane dot, R8-proven rounding)
// Warp = 2 rows x 16 candidates; 16 rows per block (256 thr).
// ---------------------------------------------------------------------------
#define EH_STRIDE (DIMK + 4)   // padded: 2-way max bank conflict

__global__ void __launch_bounds__(256)
rerank_kernel(float* __restrict__ src_p, float* __restrict__ dst_p,
              float* __restrict__ w_p)
{
    __shared__ float eh_s[16][EH_STRIDE];
    __shared__ float cv[16][CAND];
    __shared__ int   cix[16][CAND];

    const int tid = threadIdx.x, wid = tid >> 5, lane = tid & 31;
    const int rowblk = blockIdx.x * 16;

    for (int i = tid; i < 16 * (DIMK / 4); i += 256) {
        int r = i >> 7, u = (i & 127) * 4;
        *(float4*)&eh_s[r][u] = *(const float4*)(g_eh + (size_t)(rowblk + r) * DIMK + u);
    }
    __syncthreads();

    const int lr   = lane >> 4;          // 0/1: which of the warp's 2 rows
    const int lc   = lane & 15;          // candidate slot
    const int rloc = wid * 2 + lr;       // local row 0..15
    const int row  = rowblk + rloc;

    const int cand = g_cand[(size_t)row * CAND + lc];
    const float* bt = g_et + (size_t)cand * DIMK;
    const float* ah = eh_s[rloc];

    // strictly k-sequential fp32 accumulation (empirically flip-free vs JAX)
    float acc = 0.f;
    #pragma unroll 8
    for (int k = 0; k < DIMK; k += 4) {
        float4 b = *(const float4*)(bt + k);
        acc = fmaf(ah[k],     b.x, acc);
        acc = fmaf(ah[k + 1], b.y, acc);
        acc = fmaf(ah[k + 2], b.z, acc);
        acc = fmaf(ah[k + 3], b.w, acc);
    }
    cv[rloc][lc]  = acc * SCALE;     // post-scale, matching jax (e_h@e_t.T)*scale
    cix[rloc][lc] = cand;
    __syncwarp();

    if (lc == 0) {                   // lanes 0 and 16: one per row
        float tv[KTOP]; int ti[KTOP];
        #pragma unroll
        for (int j = 0; j < KTOP; j++) { tv[j] = -INFINITY; ti[j] = 0x7FFFFFFF; }
        for (int c = 0; c < CAND; c++) {
            float v = cv[rloc][c]; int ix = cix[rloc][c];
            if (v > tv[KTOP - 1] || (v == tv[KTOP - 1] && ix < ti[KTOP - 1])) {
                int j = KTOP - 1;
                while (j > 0 && (v > tv[j - 1] || (v == tv[j - 1] && ix < ti[j - 1]))) {
                    tv[j] = tv[j - 1]; ti[j] = ti[j - 1]; j--;
                }
                tv[j] = v; ti[j] = ix;
            }
        }
        float m = tv[0];
        float e[KTOP]; float s = 0.f;
        #pragma unroll
        for (int j = 0; j < KTOP; j++) { e[j] = expf(tv[j] - m); s += e[j]; }
        #pragma unroll
        for (int j = 0; j < KTOP; j++) {
            int o = row * KTOP + j;
            if (src_p) src_p[o] = (float)row;
            if (dst_p) dst_p[o] = (float)ti[j];
            if (w_p)   w_p[o]   = e[j] / s;
        }
    }
}

// ---------------------------------------------------------------------------
extern "C" void kernel_launch(void* const* d_in, const int* in_sizes, int n_in,
                              void* d_out, int out_size)
{
    const float* X  = (const float*)d_in[0];
    const float* Wh = (const float*)d_in[1];
    const float* bh = (const float*)d_in[2];
    const float* Wt = (const float*)d_in[3];
    const float* bt = (const float*)d_in[4];

    cudaFuncSetAttribute(logits_cand_kernel,
                         cudaFuncAttributeMaxDynamicSharedMemorySize, SMEM_LG);

    embed_kernel<<<dim3(DIMK / 128, NROWS / 64, 2), 256>>>(X, Wh, bh, Wt, bt);
    logits_cand_kernel<<<NROWS / MBLK, 512, SMEM_LG>>>();

    const int NK = NROWS * KTOP;   // 81920
    float* out = (float*)d_out;
    float *sp = nullptr, *dp = nullptr, *wp = nullptr;
    if (out_size >= 3 * NK)      { sp = out; dp = out + NK; wp = out + 2 * NK; }
    else if (out_size == 2 * NK) { sp = out; dp = out + NK; }
    else                         { wp = out; }

    rerank_kernel<<<NROWS / 16, 256>>>(sp, dp, wp);
}

// round 17
// speedup vs baseline: 1.0481x; 1.0481x over previous
#include <cuda_runtime.h>
#include <cuda_bf16.h>
#include <math.h>
#include <stdint.h>

#define NROWS 8192
#define DIMK  512
#define KTOP  10
#define CAND  16
#define SCALE 0.04419417382415922f   // 512^-0.5

// Scratch (bss): fp32 embeddings (unscaled) + bf16 copies + candidate lists
__device__ float          g_eh[NROWS * DIMK];
__device__ float          g_et[NROWS * DIMK];
__device__ __nv_bfloat16  g_bh[NROWS * DIMK];
__device__ __nv_bfloat16  g_bt[NROWS * DIMK];
__device__ int            g_cand[NROWS * CAND];

// ---------------------------------------------------------------------------
// sm_80-era primitives (base compute_103 target — no tcgen05)
// ---------------------------------------------------------------------------
__device__ __forceinline__ uint32_t smem_to_u32(const void* p) {
    uint32_t a;
    asm("{ .reg .u64 t; cvta.to.shared.u64 t, %1; cvt.u32.u64 %0, t; }" : "=r"(a) : "l"(p));
    return a;
}
__device__ __forceinline__ void ldsm4(uint32_t& r0, uint32_t& r1, uint32_t& r2, uint32_t& r3,
                                      uint32_t addr) {
    asm volatile("ldmatrix.sync.aligned.m8n8.x4.shared.b16 {%0,%1,%2,%3}, [%4];"
                 : "=r"(r0), "=r"(r1), "=r"(r2), "=r"(r3) : "r"(addr));
}
__device__ __forceinline__ void mma16816(float* c, const uint32_t* a, uint32_t b0, uint32_t b1) {
    asm volatile(
        "mma.sync.aligned.m16n8k16.row.col.f32.bf16.bf16.f32 "
        "{%0,%1,%2,%3}, {%4,%5,%6,%7}, {%8,%9}, {%0,%1,%2,%3};"
        : "+f"(c[0]), "+f"(c[1]), "+f"(c[2]), "+f"(c[3])
        : "r"(a[0]), "r"(a[1]), "r"(a[2]), "r"(a[3]), "r"(b0), "r"(b1));
}
#define CP_ASYNC16(dst, src) \
    asm volatile("cp.async.ca.shared.global [%0], [%1], 16;" :: "r"(dst), "l"(src))
#define CP_COMMIT() asm volatile("cp.async.commit_group;" ::: "memory")
#define CP_WAIT(n)  asm volatile("cp.async.wait_group %0;" :: "n"(n) : "memory")
#define SW128(b) ((b) ^ (((b) >> 3) & 0x70))

// ---------------------------------------------------------------------------
// Kernel A: E = X @ W^T + b (UNSCALED), fp32 + bf16 out. (~95% of fp32 peak)
// ---------------------------------------------------------------------------
__global__ void embed_kernel(const float* __restrict__ X,
                             const float* __restrict__ W0, const float* __restrict__ b0,
                             const float* __restrict__ W1, const float* __restrict__ b1)
{
    const int z = blockIdx.z;
    const float* W    = z ? W1 : W0;
    const float* bias = z ? b1 : b0;
    float* of         = z ? g_et : g_eh;
    __nv_bfloat16* ob = z ? g_bt : g_bh;

    __shared__ float Xs[32][64];
    __shared__ float Ws[32][128];

    const int tid = threadIdx.x;
    const int rb = blockIdx.y * 64;
    const int cb = blockIdx.x * 128;
    const int ty = tid >> 5;
    const int tx = tid & 31;

    float acc[8][4];
    #pragma unroll
    for (int i = 0; i < 8; i++)
        #pragma unroll
        for (int j = 0; j < 4; j++) acc[i][j] = 0.f;

    const int lr  = tid & 63;
    const int lk  = (tid >> 6) * 8;
    const int lrw = tid & 127;
    const int lkw = (tid >> 7) * 16;

    for (int kc = 0; kc < DIMK; kc += 32) {
        __syncthreads();
        #pragma unroll
        for (int j = 0; j < 8; j += 4) {
            float4 xv = *(const float4*)(X + (size_t)(rb + lr) * DIMK + kc + lk + j);
            Xs[lk + j + 0][lr] = xv.x; Xs[lk + j + 1][lr] = xv.y;
            Xs[lk + j + 2][lr] = xv.z; Xs[lk + j + 3][lr] = xv.w;
        }
        #pragma unroll
        for (int j = 0; j < 16; j += 4) {
            float4 wv = *(const float4*)(W + (size_t)(cb + lrw) * DIMK + kc + lkw + j);
            Ws[lkw + j + 0][lrw] = wv.x; Ws[lkw + j + 1][lrw] = wv.y;
            Ws[lkw + j + 2][lrw] = wv.z; Ws[lkw + j + 3][lrw] = wv.w;
        }
        __syncthreads();
        #pragma unroll
        for (int k = 0; k < 32; k++) {
            float4 a0 = *(const float4*)&Xs[k][ty * 8];
            float4 a1 = *(const float4*)&Xs[k][ty * 8 + 4];
            float4 b  = *(const float4*)&Ws[k][tx * 4];
            float av[8] = {a0.x, a0.y, a0.z, a0.w, a1.x, a1.y, a1.z, a1.w};
            float bv[4] = {b.x, b.y, b.z, b.w};
            #pragma unroll
            for (int i = 0; i < 8; i++)
                #pragma unroll
                for (int j = 0; j < 4; j++)
                    acc[i][j] = fmaf(av[i], bv[j], acc[i][j]);
        }
    }

    float bv[4];
    #pragma unroll
    for (int j = 0; j < 4; j++) bv[j] = bias[cb + tx * 4 + j];
    #pragma unroll
    for (int i = 0; i < 8; i++) {
        int row = rb + ty * 8 + i;
        size_t base = (size_t)row * DIMK + cb + tx * 4;
        float e[4];
        #pragma unroll
        for (int j = 0; j < 4; j++) e[j] = acc[i][j] + bv[j];
        *(float4*)(of + base) = make_float4(e[0], e[1], e[2], e[3]);
        __nv_bfloat162 p0, p1;
        p0.x = __float2bfloat16_rn(e[0]); p0.y = __float2bfloat16_rn(e[1]);
        p1.x = __float2bfloat16_rn(e[2]); p1.y = __float2bfloat16_rn(e[3]);
        *(__nv_bfloat162*)(ob + base)     = p0;
        *(__nv_bfloat162*)(ob + base + 2) = p1;
    }
}

// ---------------------------------------------------------------------------
// Kernel B: bf16 HMMA approx logits + warp-parallel register top-16 select.
// MBLK=56 rows/block, grid 147 (one full wave on 148 SMs). 512 thr, 16 warps
// (2x8 grid of 32x32 warp tiles over a 64-row padded stripe; rows 56-63 are
// computed-and-discarded padding). N-tiles of 256, KC=64, 3x32KB B ring with
// depth-1 prefetch and a SINGLE barrier per chunk. Stage in bf16.
// ---------------------------------------------------------------------------
#define MBLK   56
#define NTILE  256
#define KC     64
#define NCHUNK (DIMK / KC)                  // 8
#define NTILES (NROWS / NTILE)              // 32
#define GTOT   (NTILES * NCHUNK)            // 256 global chunks

#define OFF_A      0                        // 8 sub-tiles x 8192 B = 65536
#define OFF_B      65536                    // 3 x 32768 = 98304
#define OFF_STAGE  163840                   // 64 x 264 x 2 = 33792 (bf16)
#define STAGE_STRIDE 264                    // halfs
#define SMEM_LG    197632

__global__ void __launch_bounds__(512, 1)
logits_cand_kernel()
{
    extern __shared__ char smem[];
    const uint32_t smem_base = smem_to_u32(smem);
    const int tid  = threadIdx.x;
    const int wid  = tid >> 5;
    const int lane = tid & 31;
    const int rb   = blockIdx.x * MBLK;

    const int m_base = (wid >> 3) * 32;
    const int n_base = (wid & 7) * 32;

    __nv_bfloat16* stage = (__nv_bfloat16*)(smem + OFF_STAGE);

    // register-resident sorted top-16: warp w (<14) owns rows 4w..4w+3,
    // lanes 0..15 hold slots (sorted desc, ties idx asc); lanes 16-31 hold
    // evicted history (always < threshold, can never win an insertion ballot)
    float lv[4]; int li[4];
    #pragma unroll
    for (int q = 0; q < 4; q++) { lv[q] = -INFINITY; li[q] = 0; }

    const int mat = lane >> 3, r8 = lane & 7;
    const int aoff_m = ((mat & 1) << 3) + r8;
    const int aoff_k = (mat >> 1) << 4;
    const int boff_n = ((mat >> 1) << 3) + r8;
    const int boff_k = (mat & 1) << 4;

    // A stripe: 56 real rows x 512 k bf16 -> 8 sub-tiles (3584 units, 7/thr)
    #pragma unroll
    for (int t = 0; t < 7; t++) {
        int idx = tid + t * 512;
        int c = idx / 448, rem = idx % 448, r = rem >> 3, g = rem & 7;
        int gr = rb + r; if (gr > NROWS - 1) gr = NROWS - 1;   // clamp (pad blocks)
        const __nv_bfloat16* src = g_bh + (size_t)gr * DIMK + c * KC + g * 8;
        uint32_t dst = smem_base + OFF_A + c * 8192 + SW128(r * 128 + g * 16);
        CP_ASYNC16(dst, src);
    }

    auto issue_B = [&](int g) {
        const int cbase = (g >> 3) * NTILE;
        const int koff  = (g & 7) * KC;
        const int buf   = g % 3;
        #pragma unroll
        for (int t = 0; t < 4; t++) {
            int rem = tid + t * 512;
            int r = rem >> 3, gg = rem & 7;
            const __nv_bfloat16* src = g_bt + (size_t)(cbase + r) * DIMK + koff + gg * 8;
            uint32_t dst = smem_base + OFF_B + buf * 32768 + SW128(r * 128 + gg * 16);
            CP_ASYNC16(dst, src);
        }
    };

    issue_B(0); CP_COMMIT();     // group 0: A stripe + B chunk 0

    float acc[2][4][4];

    for (int ct = 0; ct < NTILES; ct++) {
        const int cbase = ct * NTILE;

        #pragma unroll
        for (int fm = 0; fm < 2; fm++)
            #pragma unroll
            for (int fn = 0; fn < 4; fn++)
                #pragma unroll
                for (int q = 0; q < 4; q++) acc[fm][fn][q] = 0.f;

        for (int kc = 0; kc < NCHUNK; kc++) {
            const int g = ct * NCHUNK + kc;
            // issue into buf (g+1)%3: its previous readers (chunk g-2) all
            // passed chunk g-1's barrier before we got here — no race.
            if (g + 1 < GTOT) { issue_B(g + 1); CP_COMMIT(); CP_WAIT(1); }
            else              { CP_WAIT(0); }
            __syncthreads();     // single barrier per chunk

            const uint32_t Ab = smem_base + OFF_A + kc * 8192;
            const uint32_t Bb = smem_base + OFF_B + (g % 3) * 32768;

            #pragma unroll
            for (int k16 = 0; k16 < KC / 16; k16++) {
                const int kbyte = k16 * 32;
                uint32_t Af[2][4];
                #pragma unroll
                for (int fm = 0; fm < 2; fm++)
                    ldsm4(Af[fm][0], Af[fm][1], Af[fm][2], Af[fm][3],
                          Ab + SW128((m_base + fm * 16 + aoff_m) * 128 + kbyte + aoff_k));
                uint32_t Bf[2][4];
                #pragma unroll
                for (int fp = 0; fp < 2; fp++)
                    ldsm4(Bf[fp][0], Bf[fp][1], Bf[fp][2], Bf[fp][3],
                          Bb + SW128((n_base + fp * 16 + boff_n) * 128 + kbyte + boff_k));
                #pragma unroll
                for (int fm = 0; fm < 2; fm++) {
                    mma16816(acc[fm][0], Af[fm], Bf[0][0], Bf[0][1]);
                    mma16816(acc[fm][1], Af[fm], Bf[0][2], Bf[0][3]);
                    mma16816(acc[fm][2], Af[fm], Bf[1][0], Bf[1][1]);
                    mma16816(acc[fm][3], Af[fm], Bf[1][2], Bf[1][3]);
                }
            }
        }

        // stage 64x256 approx logits as bf16 (stride 264 halfs)
        #pragma unroll
        for (int fm = 0; fm < 2; fm++)
            #pragma unroll
            for (int fn = 0; fn < 4; fn++) {
                int row = m_base + fm * 16 + (lane >> 2);
                int col = n_base + fn * 8 + (lane & 3) * 2;
                __nv_bfloat162 p0, p1;
                p0.x = __float2bfloat16_rn(acc[fm][fn][0]);
                p0.y = __float2bfloat16_rn(acc[fm][fn][1]);
                p1.x = __float2bfloat16_rn(acc[fm][fn][2]);
                p1.y = __float2bfloat16_rn(acc[fm][fn][3]);
                *(__nv_bfloat162*)(stage + row * STAGE_STRIDE + col)       = p0;
                *(__nv_bfloat162*)(stage + (row + 8) * STAGE_STRIDE + col) = p1;
            }
        __syncthreads();

        // warp-parallel select: warps 0..13 handle rows 4w..4w+3 (<56)
        if (wid < 14) {
            #pragma unroll
            for (int q = 0; q < 4; q++) {
                const int row = wid * 4 + q;
                const __nv_bfloat16* crow = stage + row * STAGE_STRIDE;
                float kv = __shfl_sync(0xffffffffu, lv[q], CAND - 1);
                #pragma unroll
                for (int j = 0; j < 4; j++) {
                    float2 v2 = __bfloat1622float2(
                        *(const __nv_bfloat162*)(crow + 64 * j + lane * 2));
                    #pragma unroll
                    for (int h = 0; h < 2; h++) {
                        float v = h ? v2.y : v2.x;
                        unsigned m = __ballot_sync(0xffffffffu, v > kv);
                        while (m) {
                            int b = __ffs(m) - 1; m &= m - 1;
                            float vb = __shfl_sync(0xffffffffu, v, b);
                            int   cb = cbase + 64 * j + 2 * b + h;
                            unsigned gt = __ballot_sync(0xffffffffu,
                                (lv[q] > vb) || (lv[q] == vb && li[q] < cb));
                            int p = __popc(gt);
                            if (p < CAND) {
                                float pv = __shfl_up_sync(0xffffffffu, lv[q], 1);
                                int   pi = __shfl_up_sync(0xffffffffu, li[q], 1);
                                if (lane > p)  { lv[q] = pv; li[q] = pi; }
                                if (lane == p) { lv[q] = vb; li[q] = cb; }
                                kv = __shfl_sync(0xffffffffu, lv[q], CAND - 1);
                            }
                        }
                    }
                }
            }
        }
        // stage rewrite is >= NCHUNK barriers away — safe
    }

    if (wid < 14) {
        #pragma unroll
        for (int q = 0; q < 4; q++) {
            int row = rb + wid * 4 + q;
            if (lane < CAND && row < NROWS)
                g_cand[(size_t)row * CAND + lane] = li[q];
        }
    }
}

// ---------------------------------------------------------------------------
// Kernel C: EXACT fp32 rerank (k-sequential per-lane dot, R8-proven rounding)
// Warp = 2 rows x 16 candidates; 16 rows per block (256 thr).
// ---------------------------------------------------------------------------
#define EH_STRIDE (DIMK + 4)   // padded: 2-way max bank conflict

__global__ void __launch_bounds__(256)
rerank_kernel(float* __restrict__ src_p, float* __restrict__ dst_p,
              float* __restrict__ w_p)
{
    __shared__ float eh_s[16][EH_STRIDE];
    __shared__ float cv[16][CAND];
    __shared__ int   cix[16][CAND];

    const int tid = threadIdx.x, wid = tid >> 5, lane = tid & 31;
    const int rowblk = blockIdx.x * 16;

    for (int i = tid; i < 16 * (DIMK / 4); i += 256) {
        int r = i >> 7, u = (i & 127) * 4;
        *(float4*)&eh_s[r][u] = *(const float4*)(g_eh + (size_t)(rowblk + r) * DIMK + u);
    }
    __syncthreads();

    const int lr   = lane >> 4;
    const int lc   = lane & 15;
    const int rloc = wid * 2 + lr;
    const int row  = rowblk + rloc;

    const int cand = g_cand[(size_t)row * CAND + lc];
    const float* bt = g_et + (size_t)cand * DIMK;
    const float* ah = eh_s[rloc];

    // strictly k-sequential fp32 accumulation (empirically flip-free vs JAX)
    float acc = 0.f;
    #pragma unroll 8
    for (int k = 0; k < DIMK; k += 4) {
        float4 b = *(const float4*)(bt + k);
        acc = fmaf(ah[k],     b.x, acc);
        acc = fmaf(ah[k + 1], b.y, acc);
        acc = fmaf(ah[k + 2], b.z, acc);
        acc = fmaf(ah[k + 3], b.w, acc);
    }
    cv[rloc][lc]  = acc * SCALE;     // post-scale, matching jax (e_h@e_t.T)*scale
    cix[rloc][lc] = cand;
    __syncwarp();

    if (lc == 0) {
        float tv[KTOP]; int ti[KTOP];
        #pragma unroll
        for (int j = 0; j < KTOP; j++) { tv[j] = -INFINITY; ti[j] = 0x7FFFFFFF; }
        for (int c = 0; c < CAND; c++) {
            float v = cv[rloc][c]; int ix = cix[rloc][c];
            if (v > tv[KTOP - 1] || (v == tv[KTOP - 1] && ix < ti[KTOP - 1])) {
                int j = KTOP - 1;
                while (j > 0 && (v > tv[j - 1] || (v == tv[j - 1] && ix < ti[j - 1]))) {
                    tv[j] = tv[j - 1]; ti[j] = ti[j - 1]; j--;
                }
                tv[j] = v; ti[j] = ix;
            }
        }
        float m = tv[0];
        float e[KTOP]; float s = 0.f;
        #pragma unroll
        for (int j = 0; j < KTOP; j++) { e[j] = expf(tv[j] - m); s += e[j]; }
        #pragma unroll
        for (int j = 0; j < KTOP; j++) {
            int o = row * KTOP + j;
            if (src_p) src_p[o] = (float)row;
            if (dst_p) dst_p[o] = (float)ti[j];
            if (w_p)   w_p[o]   = e[j] / s;
        }
    }
}

// ---------------------------------------------------------------------------
extern "C" void kernel_launch(void* const* d_in, const int* in_sizes, int n_in,
                              void* d_out, int out_size)
{
    const float* X  = (const float*)d_in[0];
    const float* Wh = (const float*)d_in[1];
    const float* bh = (const float*)d_in[2];
    const float* Wt = (const float*)d_in[3];
    const float* bt = (const float*)d_in[4];

    cudaFuncSetAttribute(logits_cand_kernel,
                         cudaFuncAttributeMaxDynamicSharedMemorySize, SMEM_LG);

    embed_kernel<<<dim3(DIMK / 128, NROWS / 64, 2), 256>>>(X, Wh, bh, Wt, bt);

    const int grid_cand = (NROWS + MBLK - 1) / MBLK;   // 147
    logits_cand_kernel<<<grid_cand, 512, SMEM_LG>>>();

    const int NK = NROWS * KTOP;   // 81920
    float* out = (float*)d_out;
    float *sp = nullptr, *dp = nullptr, *wp = nullptr;
    if (out_size >= 3 * NK)      { sp = out; dp = out + NK; wp = out + 2 * NK; }
    else if (out_size == 2 * NK) { sp = out; dp = out + NK; }
    else                         { wp = out; }

    rerank_kernel<<<NROWS / 16, 256>>>(sp, dp, wp);
}